// round 1
// baseline (speedup 1.0000x reference)
#include <cuda_runtime.h>
#include <cuda_bf16.h>

#define P_LVL 16
#define B_DIM 64
#define T_DIM 512
#define NS 48
#define NS2 (NS*NS)
#define GRP 2

// Scratch (static device allocations are allowed)
__device__ float g_expT[NS2], g_expL[NS2], g_expR[NS2];
__device__ float g_llT[P_LVL * B_DIM];   // 1024
__device__ float g_llL[T_DIM * B_DIM];   // 32768
__device__ float g_llR[T_DIM * B_DIM];   // 32768

__global__ void prep_exp_kernel(const float* __restrict__ tT,
                                const float* __restrict__ tL,
                                const float* __restrict__ tR) {
    int i = blockIdx.x * blockDim.x + threadIdx.x;
    if (i < NS2) {
        g_expT[i] = expf(tT[i]);
        g_expL[i] = expf(tL[i]);
        g_expR[i] = expf(tR[i]);
    }
}

// One sequence per 48-thread group; lane j owns state j.
// Linear-domain CRF forward with normalization folded into next step's dot.
__global__ __launch_bounds__(NS * GRP) void crf_fwd_kernel(
    const float* __restrict__ logits,
    const float* __restrict__ trT,
    const float* __restrict__ trL,
    const float* __restrict__ trR,
    const int*   __restrict__ tags)
{
    const int j = threadIdx.x;   // state 0..47
    const int g = threadIdx.y;   // group in block

    __shared__ __align__(16) float s_u[2][GRP][NS];
    __shared__ float s_sc[GRP][NS];
    __shared__ float s_trans[NS2];

    const int bid = blockIdx.x;
    int mode, sid;
    const float* traw;
    const float* texp;
    float* outp;
    if (bid < 512)              { mode = 0; sid = bid * GRP + g;               traw = trT; texp = g_expT; outp = g_llT; }
    else if (bid < 512 + 16384) { mode = 1; sid = (bid - 512) * GRP + g;       traw = trL; texp = g_expL; outp = g_llL; }
    else                        { mode = 2; sid = (bid - 16896) * GRP + g;     traw = trR; texp = g_expR; outp = g_llR; }

    // raw trans into smem (for score gathers)
    for (int k = j + g * NS; k < NS2; k += NS * GRP) s_trans[k] = traw[k];

    int base, estride, tbase, tstride, len;
    if (mode == 0) {
        // sequence over time axis; sid = p*64 + b; length T - p
        int p = sid >> 6;
        base    = sid * (T_DIM * NS);
        estride = NS;
        tbase   = sid * T_DIM;
        tstride = 1;
        len     = T_DIM - p;
    } else {
        int t = sid >> 6;
        int b = sid & 63;
        if (mode == 1) {
            // sequence over levels p at fixed (b,t); valid p < T - t
            base    = (b * T_DIM + t) * NS;
            estride = B_DIM * T_DIM * NS;
            tbase   = b * T_DIM + t;
            tstride = B_DIM * T_DIM;
            len     = min(P_LVL, T_DIM - t);
        } else {
            // rolled: level p uses time t-p; valid p <= t
            base    = (b * T_DIM + t) * NS;
            estride = B_DIM * T_DIM * NS - NS;
            tbase   = b * T_DIM + t;
            tstride = B_DIM * T_DIM - 1;
            len     = min(P_LVL, t + 1);
        }
    }

    // E column for my state j, in registers
    float Ecol[NS];
#pragma unroll
    for (int i = 0; i < NS; i++) Ecol[i] = texp[i * NS + j];

    const float* ep = logits + base + j;
    const int*   tp = tags + tbase;

    // t = 0 init
    float e0  = ep[0];
    int   tg0 = tp[0];
    ep += estride; tp += tstride;

    s_u[0][g][j] = e0;
    float score = (j == tg0) ? e0 : 0.f;
    int tagprev = tg0;
    __syncthreads();
    float m0 = s_u[0][g][0];
    float C  = m0;
    s_u[1][g][j] = __expf(e0 - m0);
    __syncthreads();

    int cur = 1;
    float em = 0.f;
    int   tg = 0;
    if (len > 1) { em = ep[0]; tg = tp[0]; }

    for (int t = 1; t < len; t++) {
        ep += estride; tp += tstride;
        bool  more = (t + 1) < len;
        float em_n = more ? ep[0] : 0.f;   // predicated prefetch (avoids OOB)
        int   tg_n = more ? tp[0] : 0;

        const float* w = s_u[cur][g];
        float a0 = 0.f, a1 = 0.f, a2 = 0.f, a3 = 0.f;
#pragma unroll
        for (int i = 0; i < NS; i += 4) {
            float4 wv = *reinterpret_cast<const float4*>(w + i);
            a0 = fmaf(wv.x, Ecol[i + 0], a0);
            a1 = fmaf(wv.y, Ecol[i + 1], a1);
            a2 = fmaf(wv.z, Ecol[i + 2], a2);
            a3 = fmaf(wv.w, Ecol[i + 3], a3);
        }
        float dot = (a0 + a1) + (a2 + a3);
        float u0  = w[0];
        float tr  = s_trans[tagprev * NS + j];

        C += __logf(u0);
        float unew = dot * __expf(em) * __fdividef(1.f, u0);
        score += (j == tg) ? (em + tr) : 0.f;
        tagprev = tg;

        s_u[cur ^ 1][g][j] = unew;   // write opposite buffer
        __syncthreads();             // one barrier/step (double buffered)
        cur ^= 1;
        em = em_n; tg = tg_n;
    }

    s_sc[g][j] = score;
    __syncthreads();
    if (j == 0) {
        const float* uf = s_u[cur][g];
        float s = 0.f;
#pragma unroll
        for (int i = 0; i < NS; i++) s += uf[i];
        float sc = 0.f;
#pragma unroll
        for (int i = 0; i < NS; i++) sc += s_sc[g][i];
        outp[sid] = sc - (logf(s) + C);   // ll = score - log_den
    }
}

// Deterministic final reduction in double (serial fp32 sum of 32768 x ~70
// against a ~2.3e6 total would already risk the 1e-3 bound; atomics would
// be non-deterministic).
__global__ void reduce_kernel(float* __restrict__ out) {
    __shared__ double sd[256];
    const int which = blockIdx.x;
    const float* src = (which == 0) ? g_llT : (which == 1) ? g_llL : g_llR;
    const int n = (which == 0) ? (P_LVL * B_DIM) : (T_DIM * B_DIM);
    double a = 0.0;
    for (int i = threadIdx.x; i < n; i += blockDim.x) a += (double)src[i];
    sd[threadIdx.x] = a;
    __syncthreads();
    for (int s = blockDim.x / 2; s > 0; s >>= 1) {
        if (threadIdx.x < s) sd[threadIdx.x] += sd[threadIdx.x + s];
        __syncthreads();
    }
    if (threadIdx.x == 0) out[which] = (float)(-sd[0]);
}

extern "C" void kernel_launch(void* const* d_in, const int* in_sizes, int n_in,
                              void* d_out, int out_size) {
    const float* logits = (const float*)d_in[0];
    const float* trT    = (const float*)d_in[1];
    const float* trL    = (const float*)d_in[2];
    const float* trR    = (const float*)d_in[3];
    const int*   tags   = (const int*)d_in[4];
    // d_in[5] = mask: analytic (t < T - p), not read.

    prep_exp_kernel<<<(NS2 + 255) / 256, 256>>>(trT, trL, trR);

    dim3 blk(NS, GRP);
    crf_fwd_kernel<<<512 + 2 * 16384, blk>>>(logits, trT, trL, trR, tags);

    reduce_kernel<<<3, 256>>>((float*)d_out);
}

// round 2
// speedup vs baseline: 1.0037x; 1.0037x over previous
#include <cuda_runtime.h>
#include <cuda_bf16.h>

#define P_LVL 16
#define B_DIM 64
#define T_DIM 512
#define NS 48
#define NS2 (NS*NS)
#define GRP 2

// Scratch (static device allocations are allowed)
__device__ float g_expT[NS2], g_expL[NS2], g_expR[NS2];
__device__ float g_llT[P_LVL * B_DIM];   // 1024
__device__ float g_llL[T_DIM * B_DIM];   // 32768
__device__ float g_llR[T_DIM * B_DIM];   // 32768

__global__ void prep_exp_kernel(const float* __restrict__ tT,
                                const float* __restrict__ tL,
                                const float* __restrict__ tR) {
    int i = blockIdx.x * blockDim.x + threadIdx.x;
    if (i < NS2) {
        g_expT[i] = expf(tT[i]);
        g_expL[i] = expf(tL[i]);
        g_expR[i] = expf(tR[i]);
    }
}

// One sequence per 48-thread group; lane j owns state j.
// Linear-domain CRF forward with normalization folded into next step's dot.
__global__ __launch_bounds__(NS * GRP) void crf_fwd_kernel(
    const float* __restrict__ logits,
    const float* __restrict__ trT,
    const float* __restrict__ trL,
    const float* __restrict__ trR,
    const int*   __restrict__ tags)
{
    const int j = threadIdx.x;   // state 0..47
    const int g = threadIdx.y;   // group in block

    __shared__ __align__(16) float s_u[2][GRP][NS];
    __shared__ float s_sc[GRP][NS];
    __shared__ float s_trans[NS2];

    const int bid = blockIdx.x;
    int mode, sid;
    const float* traw;
    const float* texp;
    float* outp;
    if (bid < 512)              { mode = 0; sid = bid * GRP + g;               traw = trT; texp = g_expT; outp = g_llT; }
    else if (bid < 512 + 16384) { mode = 1; sid = (bid - 512) * GRP + g;       traw = trL; texp = g_expL; outp = g_llL; }
    else                        { mode = 2; sid = (bid - 16896) * GRP + g;     traw = trR; texp = g_expR; outp = g_llR; }

    // raw trans into smem (for score gathers)
    for (int k = j + g * NS; k < NS2; k += NS * GRP) s_trans[k] = traw[k];

    int base, estride, tbase, tstride, len;
    if (mode == 0) {
        // sequence over time axis; sid = p*64 + b; length T - p
        int p = sid >> 6;
        base    = sid * (T_DIM * NS);
        estride = NS;
        tbase   = sid * T_DIM;
        tstride = 1;
        len     = T_DIM - p;
    } else {
        int t = sid >> 6;
        int b = sid & 63;
        if (mode == 1) {
            // sequence over levels p at fixed (b,t); valid p < T - t
            base    = (b * T_DIM + t) * NS;
            estride = B_DIM * T_DIM * NS;
            tbase   = b * T_DIM + t;
            tstride = B_DIM * T_DIM;
            len     = min(P_LVL, T_DIM - t);
        } else {
            // rolled: level p uses time t-p; valid p <= t
            base    = (b * T_DIM + t) * NS;
            estride = B_DIM * T_DIM * NS - NS;
            tbase   = b * T_DIM + t;
            tstride = B_DIM * T_DIM - 1;
            len     = min(P_LVL, t + 1);
        }
    }

    // E column for my state j, in registers
    float Ecol[NS];
#pragma unroll
    for (int i = 0; i < NS; i++) Ecol[i] = texp[i * NS + j];

    const float* ep = logits + base + j;
    const int*   tp = tags + tbase;

    // t = 0 init
    float e0  = ep[0];
    int   tg0 = tp[0];
    ep += estride; tp += tstride;

    s_u[0][g][j] = e0;
    float score = (j == tg0) ? e0 : 0.f;
    int tagprev = tg0;
    __syncthreads();
    float m0 = s_u[0][g][0];
    float C  = m0;
    s_u[1][g][j] = __expf(e0 - m0);
    __syncthreads();

    int cur = 1;
    float em = 0.f;
    int   tg = 0;
    if (len > 1) { em = ep[0]; tg = tp[0]; }

    for (int t = 1; t < len; t++) {
        ep += estride; tp += tstride;
        bool  more = (t + 1) < len;
        float em_n = more ? ep[0] : 0.f;   // predicated prefetch (avoids OOB)
        int   tg_n = more ? tp[0] : 0;

        const float* w = s_u[cur][g];
        float a0 = 0.f, a1 = 0.f, a2 = 0.f, a3 = 0.f;
#pragma unroll
        for (int i = 0; i < NS; i += 4) {
            float4 wv = *reinterpret_cast<const float4*>(w + i);
            a0 = fmaf(wv.x, Ecol[i + 0], a0);
            a1 = fmaf(wv.y, Ecol[i + 1], a1);
            a2 = fmaf(wv.z, Ecol[i + 2], a2);
            a3 = fmaf(wv.w, Ecol[i + 3], a3);
        }
        float dot = (a0 + a1) + (a2 + a3);
        float u0  = w[0];
        float tr  = s_trans[tagprev * NS + j];

        C += __logf(u0);
        float unew = dot * __expf(em) * __fdividef(1.f, u0);
        score += (j == tg) ? (em + tr) : 0.f;
        tagprev = tg;

        s_u[cur ^ 1][g][j] = unew;   // write opposite buffer
        __syncthreads();             // one barrier/step (double buffered)
        cur ^= 1;
        em = em_n; tg = tg_n;
    }

    s_sc[g][j] = score;
    __syncthreads();
    if (j == 0) {
        const float* uf = s_u[cur][g];
        float s = 0.f;
#pragma unroll
        for (int i = 0; i < NS; i++) s += uf[i];
        float sc = 0.f;
#pragma unroll
        for (int i = 0; i < NS; i++) sc += s_sc[g][i];
        outp[sid] = sc - (logf(s) + C);   // ll = score - log_den
    }
}

// Deterministic final reduction in double (serial fp32 sum of 32768 x ~70
// against a ~2.3e6 total would already risk the 1e-3 bound; atomics would
// be non-deterministic).
__global__ void reduce_kernel(float* __restrict__ out) {
    __shared__ double sd[256];
    const int which = blockIdx.x;
    const float* src = (which == 0) ? g_llT : (which == 1) ? g_llL : g_llR;
    const int n = (which == 0) ? (P_LVL * B_DIM) : (T_DIM * B_DIM);
    double a = 0.0;
    for (int i = threadIdx.x; i < n; i += blockDim.x) a += (double)src[i];
    sd[threadIdx.x] = a;
    __syncthreads();
    for (int s = blockDim.x / 2; s > 0; s >>= 1) {
        if (threadIdx.x < s) sd[threadIdx.x] += sd[threadIdx.x + s];
        __syncthreads();
    }
    if (threadIdx.x == 0) out[which] = (float)(-sd[0]);
}

extern "C" void kernel_launch(void* const* d_in, const int* in_sizes, int n_in,
                              void* d_out, int out_size) {
    const float* logits = (const float*)d_in[0];
    const float* trT    = (const float*)d_in[1];
    const float* trL    = (const float*)d_in[2];
    const float* trR    = (const float*)d_in[3];
    const int*   tags   = (const int*)d_in[4];
    // d_in[5] = mask: analytic (t < T - p), not read.

    prep_exp_kernel<<<(NS2 + 255) / 256, 256>>>(trT, trL, trR);

    dim3 blk(NS, GRP);
    crf_fwd_kernel<<<512 + 2 * 16384, blk>>>(logits, trT, trL, trR, tags);

    reduce_kernel<<<3, 256>>>((float*)d_out);
}

// round 5
// speedup vs baseline: 1.1254x; 1.1213x over previous
#include <cuda_runtime.h>
#include <cuda_bf16.h>

#define P_LVL 16
#define B_DIM 64
#define T_DIM 512
#define NS 48
#define NS2 (NS*NS)
#define GRP 2

// ---- packed f32x2 helpers (FFMA2 path, PTX-only per SASS_QUICKREF) ----
#define FMA2(acc, a, b) asm("fma.rn.f32x2 %0, %1, %2, %0;" : "+l"(acc) : "l"(a), "l"(b))
#define ADD2(d, a, b)   asm("add.rn.f32x2 %0, %1, %2;"      : "=l"(d)  : "l"(a), "l"(b))
#define PACK2(d, lo, hi) asm("mov.b64 %0, {%1, %2};"        : "=l"(d)  : "f"(lo), "f"(hi))
#define UNPK2(lo, hi, v) asm("mov.b64 {%0, %1}, %2;"        : "=f"(lo), "=f"(hi) : "l"(v))

// Scratch (static device allocations are allowed)
__device__ float g_expT[NS2], g_expL[NS2], g_expR[NS2];
__device__ float g_llT[P_LVL * B_DIM];   // 1024
__device__ float g_llL[T_DIM * B_DIM];   // 32768
__device__ float g_llR[T_DIM * B_DIM];   // 32768

__global__ void prep_exp_kernel(const float* __restrict__ tT,
                                const float* __restrict__ tL,
                                const float* __restrict__ tR) {
    int i = blockIdx.x * blockDim.x + threadIdx.x;
    if (i < NS2) {
        g_expT[i] = expf(tT[i]);
        g_expL[i] = expf(tL[i]);
        g_expR[i] = expf(tR[i]);
    }
}

// Persistent-block CRF forward. One sequence per 48-thread group (lane j owns
// state j); linear-domain recursion with power-of-two renormalization
// (integer exponent accumulation; no log/rcp MUFU in the loop).
// Grid layout:
//   blocks [0, 512)        : mode 0 (time axis), 1 pair-job each
//   blocks [512, 2560)     : mode 1 (level axis), 8 pair-jobs each
//   blocks [2560, 4608)    : mode 2 (rolled level axis), 8 pair-jobs each
// A pair-job j covers sids {2j, 2j+1}, which always share the same length.
__global__ __launch_bounds__(NS * GRP, 8) void crf_fwd_kernel(
    const float* __restrict__ logits,
    const float* __restrict__ trT,
    const float* __restrict__ trL,
    const float* __restrict__ trR,
    const int*   __restrict__ tags)
{
    const int j = threadIdx.x;   // state 0..47
    const int g = threadIdx.y;   // group in block

    __shared__ __align__(16) float s_u[2][GRP][NS];
    __shared__ float s_sc[GRP][NS];
    __shared__ float s_trans[NS2];

    const int bid = blockIdx.x;
    int mode, job0, job1;
    const float* traw;
    const float* texp;
    float* outp;
    if (bid < 512) {
        mode = 0; job0 = bid; job1 = bid + 1;
        traw = trT; texp = g_expT; outp = g_llT;
    } else if (bid < 512 + 2048) {
        mode = 1; job0 = (bid - 512) * 8; job1 = job0 + 8;
        traw = trL; texp = g_expL; outp = g_llL;
    } else {
        mode = 2; job0 = (bid - 2560) * 8; job1 = job0 + 8;
        traw = trR; texp = g_expR; outp = g_llR;
    }

    // raw trans into smem (for score gathers)
    for (int k = j + g * NS; k < NS2; k += NS * GRP) s_trans[k] = traw[k];

    // E column for my state j, packed into 24 f32x2 registers
    unsigned long long Epk[NS / 2];
#pragma unroll
    for (int k = 0; k < NS / 2; k++) {
        float lo = texp[(2 * k) * NS + j];
        float hi = texp[(2 * k + 1) * NS + j];
        PACK2(Epk[k], lo, hi);
    }
    __syncthreads();

    for (int job = job0; job < job1; ++job) {
        const int sid = job * 2 + g;
        int base, estride, tbase, tstride, len;
        if (mode == 0) {
            int p = sid >> 6;
            base    = sid * (T_DIM * NS);
            estride = NS;
            tbase   = sid * T_DIM;
            tstride = 1;
            len     = T_DIM - p;
        } else {
            int t = sid >> 6;
            int b = sid & 63;
            if (mode == 1) {
                base    = (b * T_DIM + t) * NS;
                estride = B_DIM * T_DIM * NS;
                tbase   = b * T_DIM + t;
                tstride = B_DIM * T_DIM;
                len     = min(P_LVL, T_DIM - t);
            } else {
                base    = (b * T_DIM + t) * NS;
                estride = B_DIM * T_DIM * NS - NS;
                tbase   = b * T_DIM + t;
                tstride = B_DIM * T_DIM - 1;
                len     = min(P_LVL, t + 1);
            }
        }

        const float* ep = logits + base + j;
        const int*   tp = tags + tbase;

        // t = 0 init: no max-normalization needed (|e0| <= ~6 after masking is
        // never visited; valid logits ~N(0,1)), C starts at 0.
        float e0  = ep[0];
        int   tg0 = tp[0];
        float score = (j == tg0) ? e0 : 0.f;
        int   tagprev = tg0;
        int   Cexp = 0;
        s_u[0][g][j] = __expf(e0);
        int cur = 0;

        ep += estride; tp += tstride;
        float em = 0.f;
        int   tg = 0;
        if (len > 1) { em = ep[0]; tg = tp[0]; }
        __syncthreads();

        for (int t = 1; t < len; t++) {
            ep += estride; tp += tstride;
            bool  more = (t + 1) < len;
            float em_n = more ? ep[0] : 0.f;   // predicated prefetch
            int   tg_n = more ? tp[0] : 0;

            const ulonglong2* w2 = reinterpret_cast<const ulonglong2*>(s_u[cur][g]);
            unsigned long long acc0 = 0ull, acc1 = 0ull;
            ulonglong2 wv0 = w2[0];
            FMA2(acc0, wv0.x, Epk[0]);
            FMA2(acc1, wv0.y, Epk[1]);
#pragma unroll
            for (int k = 1; k < 12; k++) {
                ulonglong2 wv = w2[k];
                FMA2(acc0, wv.x, Epk[2 * k]);
                FMA2(acc1, wv.y, Epk[2 * k + 1]);
            }
            unsigned long long accs;
            ADD2(accs, acc0, acc1);
            float dlo, dhi;
            UNPK2(dlo, dhi, accs);
            float dot = dlo + dhi;

            // power-of-two renormalization by u0 = w[0] (group-uniform, > 0)
            unsigned int u0b = (unsigned int)wv0.x;        // low half = w[0]
            int eexp = (int)(u0b >> 23);                   // biased exponent
            Cexp += eexp - 127;
            float scale = __uint_as_float((unsigned)(254 - eexp) << 23); // 2^-e

            float tr = s_trans[tagprev * NS + j];
            float unew = dot * (__expf(em) * scale);
            score += (j == tg) ? (em + tr) : 0.f;
            tagprev = tg;

            s_u[cur ^ 1][g][j] = unew;
            __syncthreads();             // one barrier/step (double buffered)
            cur ^= 1;
            em = em_n; tg = tg_n;
        }

        // epilogue: parallel partial reduction, then lane 0 finishes
        s_sc[g][j] = score;
        __syncthreads();
        if (j < 16) {
            s_sc[g][j]      += s_sc[g][j + 16]      + s_sc[g][j + 32];
            s_u[cur][g][j]  += s_u[cur][g][j + 16]  + s_u[cur][g][j + 32];
        }
        __syncthreads();
        if (j == 0) {
            float su = 0.f, sc = 0.f;
#pragma unroll
            for (int i = 0; i < 16; i++) { su += s_u[cur][g][i]; sc += s_sc[g][i]; }
            double C = (double)Cexp * 0.6931471805599453;
            outp[sid] = (float)((double)sc - ((double)logf(su) + C));
        }
        __syncthreads();   // protect s_u/s_sc reuse by next job
    }
}

// Deterministic final reduction in double (atomics would be non-deterministic;
// serial fp32 of 32768 x ~70 vs a ~2.3e6 total risks the 1e-3 bound).
__global__ void reduce_kernel(float* __restrict__ out) {
    __shared__ double sd[256];
    const int which = blockIdx.x;
    const float* src = (which == 0) ? g_llT : (which == 1) ? g_llL : g_llR;
    const int n = (which == 0) ? (P_LVL * B_DIM) : (T_DIM * B_DIM);
    double a = 0.0;
    for (int i = threadIdx.x; i < n; i += blockDim.x) a += (double)src[i];
    sd[threadIdx.x] = a;
    __syncthreads();
    for (int s = blockDim.x / 2; s > 0; s >>= 1) {
        if (threadIdx.x < s) sd[threadIdx.x] += sd[threadIdx.x + s];
        __syncthreads();
    }
    if (threadIdx.x == 0) out[which] = (float)(-sd[0]);
}

extern "C" void kernel_launch(void* const* d_in, const int* in_sizes, int n_in,
                              void* d_out, int out_size) {
    const float* logits = (const float*)d_in[0];
    const float* trT    = (const float*)d_in[1];
    const float* trL    = (const float*)d_in[2];
    const float* trR    = (const float*)d_in[3];
    const int*   tags   = (const int*)d_in[4];
    // d_in[5] = mask: analytic (t < T - p), not read.

    prep_exp_kernel<<<(NS2 + 255) / 256, 256>>>(trT, trL, trR);

    dim3 blk(NS, GRP);
    crf_fwd_kernel<<<512 + 2048 + 2048, blk>>>(logits, trT, trL, trR, tags);

    reduce_kernel<<<3, 256>>>((float*)d_out);
}

// round 7
// speedup vs baseline: 1.4312x; 1.2716x over previous
#include <cuda_runtime.h>
#include <cuda_bf16.h>

#define P_LVL 16
#define B_DIM 64
#define T_DIM 512
#define NS 48
#define NS2 (NS*NS)
#define GRP 2
#define LN2 0.6931471805599453

// ---- packed f32x2 helpers (FFMA2 path, PTX-only per SASS_QUICKREF) ----
#define FMA2(acc, a, b) asm("fma.rn.f32x2 %0, %1, %2, %0;" : "+l"(acc) : "l"(a), "l"(b))
#define ADD2(d, a, b)   asm("add.rn.f32x2 %0, %1, %2;"      : "=l"(d)  : "l"(a), "l"(b))
#define PACK2(d, lo, hi) asm("mov.b64 %0, {%1, %2};"        : "=l"(d)  : "f"(lo), "f"(hi))
#define UNPK2(lo, hi, v) asm("mov.b64 {%0, %1}, %2;"        : "=f"(lo), "=f"(hi) : "l"(v))

// Scratch (static device allocations are allowed)
__device__ float g_llT[P_LVL * B_DIM];   // 1024
__device__ float g_llL[T_DIM * B_DIM];   // 32768
__device__ float g_llR[T_DIM * B_DIM];   // 32768

struct Smem {
    float trans[NS2];                 // raw transitions (score gathers + E build)
    float u[2][GRP][2][NS];           // double-buffered alpha, 2 seqs per group
    float em[GRP][2][P_LVL][NS];      // staged emissions for modes 1/2
    float sc[GRP][2][NS];             // score partials
};

// Dual-sequence linear-domain CRF step. Lane j owns state j; power-of-two
// renormalization by u0 (group-uniform) accumulated as integer exponent.
// No barrier inside; caller synchronizes.
__device__ __forceinline__ void crf_step(
    const float* __restrict__ wA, const float* __restrict__ wB,
    float* __restrict__ oA, float* __restrict__ oB,
    const unsigned long long* __restrict__ Epk,
    float emA, float emB, int j, int& CexpA, int& CexpB)
{
    const ulonglong2* wA2 = reinterpret_cast<const ulonglong2*>(wA);
    const ulonglong2* wB2 = reinterpret_cast<const ulonglong2*>(wB);
    unsigned long long a0 = 0ull, a1 = 0ull, b0 = 0ull, b1 = 0ull;
    ulonglong2 va0 = wA2[0];
    ulonglong2 vb0 = wB2[0];
    FMA2(a0, va0.x, Epk[0]); FMA2(a1, va0.y, Epk[1]);
    FMA2(b0, vb0.x, Epk[0]); FMA2(b1, vb0.y, Epk[1]);
#pragma unroll
    for (int k = 1; k < 12; k++) {
        ulonglong2 va = wA2[k];
        ulonglong2 vb = wB2[k];
        FMA2(a0, va.x, Epk[2 * k]); FMA2(a1, va.y, Epk[2 * k + 1]);
        FMA2(b0, vb.x, Epk[2 * k]); FMA2(b1, vb.y, Epk[2 * k + 1]);
    }
    unsigned long long as, bs;
    ADD2(as, a0, a1); ADD2(bs, b0, b1);
    float alo, ahi, blo, bhi;
    UNPK2(alo, ahi, as); UNPK2(blo, bhi, bs);
    float dA = alo + ahi, dB = blo + bhi;

    unsigned int eA = ((unsigned int)va0.x) >> 23;   // biased exponent of u0(A)
    unsigned int eB = ((unsigned int)vb0.x) >> 23;
    CexpA += (int)eA - 127;
    CexpB += (int)eB - 127;
    float sA = __uint_as_float((254u - eA) << 23);   // 2^-e
    float sB = __uint_as_float((254u - eB) << 23);

    oA[j] = dA * (__expf(emA) * sA);
    oB[j] = dB * (__expf(emB) * sB);
}

// Grid layout (2304 blocks, 48x2 threads; each group runs 2 equal-len seqs):
//   [0, 256)       mode 0 (time axis):   1 quad-job/block  (sids 4b..4b+3)
//   [256, 1280)    mode 1 (level axis):  8 quad-jobs/block
//   [1280, 2304)   mode 2 (rolled):      8 quad-jobs/block
// A quad {4m..4m+3} always shares one p (mode 0) or one t (modes 1/2), hence
// one length -> all barriers in a block are perfectly aligned.
__global__ __launch_bounds__(NS * GRP, 6) void crf_fwd_kernel(
    const float* __restrict__ logits,
    const float* __restrict__ trT,
    const float* __restrict__ trL,
    const float* __restrict__ trR,
    const int*   __restrict__ tags)
{
    __shared__ Smem sm;
    const int j = threadIdx.x;           // state 0..47
    const int g = threadIdx.y;           // group in block
    const int tid = g * NS + j;

    const int bid = blockIdx.x;
    int mode, mbase, iters;
    const float* traw;
    float* outp;
    if (bid < 256)       { mode = 0; mbase = bid;               iters = 1; traw = trT; outp = g_llT; }
    else if (bid < 1280) { mode = 1; mbase = (bid - 256) * 8;   iters = 8; traw = trL; outp = g_llL; }
    else                 { mode = 2; mbase = (bid - 1280) * 8;  iters = 8; traw = trR; outp = g_llR; }

    for (int k = tid; k < NS2; k += NS * GRP) sm.trans[k] = traw[k];
    __syncthreads();

    // E column for my state j, packed into 24 f32x2 registers (built in-kernel)
    unsigned long long Epk[NS / 2];
#pragma unroll
    for (int k = 0; k < NS / 2; k++) {
        float lo = __expf(sm.trans[(2 * k) * NS + j]);
        float hi = __expf(sm.trans[(2 * k + 1) * NS + j]);
        PACK2(Epk[k], lo, hi);
    }

    for (int it = 0; it < iters; ++it) {
        const int m    = mbase + it;
        const int sidA = 4 * m + 2 * g;        // group handles sidA, sidA+1

        float spA = 0.f, spB = 0.f;
        int   CexpA = 0, CexpB = 0;
        int   cur = 0;
        int   len;

        if (mode == 0) {
            const int p = sidA >> 6;
            len = T_DIM - p;
            const int baseA = sidA * (T_DIM * NS);
            const int baseB = baseA + T_DIM * NS;
            const int* tgA = tags + sidA * T_DIM;
            const int* tgB = tgA + T_DIM;

            // score phase: lane j covers timesteps t = j, j+48, ... (MLP-rich gathers)
            for (int t = j; t < len; t += NS) {
                int a0 = tgA[t];
                int b0 = tgB[t];
                spA += logits[baseA + t * NS + a0];
                spB += logits[baseB + t * NS + b0];
                if (t + 1 < len) {
                    spA += sm.trans[a0 * NS + tgA[t + 1]];
                    spB += sm.trans[b0 * NS + tgB[t + 1]];
                }
            }

            const float* epA = logits + baseA + j;
            const float* epB = logits + baseB + j;
            sm.u[0][g][0][j] = __expf(epA[0]);
            sm.u[0][g][1][j] = __expf(epB[0]);

            // 4-deep register prefetch ring for own-state emissions
            float cA[4], cB[4];
#pragma unroll
            for (int k = 0; k < 4; k++) {
                int tl = min(1 + k, len - 1);
                cA[k] = epA[tl * NS];
                cB[k] = epB[tl * NS];
            }
            __syncthreads();

            for (int t0 = 1; t0 < len; t0 += 4) {
                float nA[4], nB[4];
#pragma unroll
                for (int k = 0; k < 4; k++) {
                    int tl = min(t0 + 4 + k, len - 1);
                    nA[k] = epA[tl * NS];
                    nB[k] = epB[tl * NS];
                }
#pragma unroll
                for (int k = 0; k < 4; k++) {
                    if (t0 + k < len) {   // block-uniform (len uniform per block)
                        crf_step(sm.u[cur][g][0], sm.u[cur][g][1],
                                 sm.u[cur ^ 1][g][0], sm.u[cur ^ 1][g][1],
                                 Epk, cA[k], cB[k], j, CexpA, CexpB);
                        __syncthreads();
                        cur ^= 1;
                    }
                }
#pragma unroll
                for (int k = 0; k < 4; k++) { cA[k] = nA[k]; cB[k] = nB[k]; }
            }
        } else {
            const int t  = sidA >> 6;
            const int bA = sidA & 63;
            int estride, tstride;
            if (mode == 1) {
                estride = B_DIM * T_DIM * NS;
                tstride = B_DIM * T_DIM;
                len     = min(P_LVL, T_DIM - t);
            } else {
                estride = B_DIM * T_DIM * NS - NS;
                tstride = B_DIM * T_DIM - 1;
                len     = min(P_LVL, t + 1);
            }
            const int baseA  = (bA * T_DIM + t) * NS;
            const int baseB  = baseA + T_DIM * NS;
            const int tbaseA = bA * T_DIM + t;
            const int tbaseB = tbaseA + T_DIM;

            // stage ALL emissions for both seqs (own state only) -> smem.
            // 32 LDGs in flight fully hide the 6MB-stride DRAM latency.
#pragma unroll
            for (int k = 0; k < P_LVL; k++) {
                int kk = min(k, len - 1);
                sm.em[g][0][k][j] = logits[baseA + kk * estride + j];
                sm.em[g][1][k][j] = logits[baseB + kk * estride + j];
            }

            // score phase: lane-per-timestep (lanes 0-15 seq A, 16-31 seq B)
            {
                int tt = j & 15;
                if (j < 32 && tt < len) {
                    bool selB = (j >= 16);
                    int tb = selB ? tbaseB : tbaseA;
                    int eb = selB ? baseB : baseA;
                    int tg0 = tags[tb + tt * tstride];
                    float sp = logits[eb + tt * estride + tg0];
                    if (tt + 1 < len) {
                        int tg1 = tags[tb + (tt + 1) * tstride];
                        sp += sm.trans[tg0 * NS + tg1];
                    }
                    if (selB) spB = sp; else spA = sp;
                }
            }

            sm.u[0][g][0][j] = __expf(sm.em[g][0][0][j]);
            sm.u[0][g][1][j] = __expf(sm.em[g][1][0][j]);
            __syncthreads();

            for (int tt = 1; tt < len; tt++) {
                crf_step(sm.u[cur][g][0], sm.u[cur][g][1],
                         sm.u[cur ^ 1][g][0], sm.u[cur ^ 1][g][1],
                         Epk, sm.em[g][0][tt][j], sm.em[g][1][tt][j],
                         j, CexpA, CexpB);
                __syncthreads();
                cur ^= 1;
            }
        }

        // ---- epilogue (both seqs) ----
        sm.sc[g][0][j] = spA;
        sm.sc[g][1][j] = spB;
        __syncthreads();
        if (j < 16) {
            sm.sc[g][0][j] += sm.sc[g][0][j + 16] + sm.sc[g][0][j + 32];
            sm.sc[g][1][j] += sm.sc[g][1][j + 16] + sm.sc[g][1][j + 32];
            float* uA = sm.u[cur][g][0];
            float* uB = sm.u[cur][g][1];
            uA[j] += uA[j + 16] + uA[j + 32];
            uB[j] += uB[j + 16] + uB[j + 32];
        }
        __syncthreads();
        if (j < 2) {
            const float* uf = sm.u[cur][g][j];
            const float* sf = sm.sc[g][j];
            float su = 0.f, sc = 0.f;
#pragma unroll
            for (int i = 0; i < 16; i++) { su += uf[i]; sc += sf[i]; }
            int Ce = (j == 0) ? CexpA : CexpB;
            outp[sidA + j] = (float)((double)sc - ((double)logf(su) + (double)Ce * LN2));
        }
        __syncthreads();   // protect smem reuse by next job
    }
}

// Deterministic final reduction in double (atomics would be non-deterministic;
// serial fp32 of 32768 x ~70 vs a ~2.3e6 total risks the 1e-3 bound).
__global__ void reduce_kernel(float* __restrict__ out) {
    __shared__ double sd[256];
    const int which = blockIdx.x;
    const float* src = (which == 0) ? g_llT : (which == 1) ? g_llL : g_llR;
    const int n = (which == 0) ? (P_LVL * B_DIM) : (T_DIM * B_DIM);
    double a = 0.0;
    for (int i = threadIdx.x; i < n; i += blockDim.x) a += (double)src[i];
    sd[threadIdx.x] = a;
    __syncthreads();
    for (int s = blockDim.x / 2; s > 0; s >>= 1) {
        if (threadIdx.x < s) sd[threadIdx.x] += sd[threadIdx.x + s];
        __syncthreads();
    }
    if (threadIdx.x == 0) out[which] = (float)(-sd[0]);
}

extern "C" void kernel_launch(void* const* d_in, const int* in_sizes, int n_in,
                              void* d_out, int out_size) {
    const float* logits = (const float*)d_in[0];
    const float* trT    = (const float*)d_in[1];
    const float* trL    = (const float*)d_in[2];
    const float* trR    = (const float*)d_in[3];
    const int*   tags   = (const int*)d_in[4];
    // d_in[5] = mask: analytic (t < T - p), not read.

    dim3 blk(NS, GRP);
    crf_fwd_kernel<<<256 + 1024 + 1024, blk>>>(logits, trT, trL, trR, tags);

    reduce_kernel<<<3, 256>>>((float*)d_out);
}

// round 9
// speedup vs baseline: 1.5536x; 1.0855x over previous
#include <cuda_runtime.h>
#include <cuda_bf16.h>

#define P_LVL 16
#define B_DIM 64
#define T_DIM 512
#define NS 48
#define NS2 (NS*NS)
#define GRP 2
#define LN2 0.6931471805599453

// ---- packed f32x2 helpers (FFMA2 path, PTX-only per SASS_QUICKREF) ----
#define FMA2(acc, a, b) asm("fma.rn.f32x2 %0, %1, %2, %0;" : "+l"(acc) : "l"(a), "l"(b))
#define ADD2(d, a, b)   asm("add.rn.f32x2 %0, %1, %2;"      : "=l"(d)  : "l"(a), "l"(b))
#define PACK2(d, lo, hi) asm("mov.b64 %0, {%1, %2};"        : "=l"(d)  : "f"(lo), "f"(hi))
#define UNPK2(lo, hi, v) asm("mov.b64 {%0, %1}, %2;"        : "=f"(lo), "=f"(hi) : "l"(v))

__device__ __align__(16) float g_llT[P_LVL * B_DIM];   // 1024
__device__ __align__(16) float g_llL[T_DIM * B_DIM];   // 32768
__device__ __align__(16) float g_llR[T_DIM * B_DIM];   // 32768

struct Smem {
    union {
        float trans[NS2];                 // mode 0: persistent (score gathers)
        float em[GRP][4][P_LVL][NS];      // modes 1/2: staged emissions (4 seqs)
    };
    float u[2][GRP][4][NS];               // double-buffered alpha
    float sc[GRP][4][NS];                 // score partials
};

// 2-seq step (mode 0). Lane j owns state j; power-of-two renorm by u0.
__device__ __forceinline__ void crf_step2(
    const float* __restrict__ wA, const float* __restrict__ wB,
    float* __restrict__ oA, float* __restrict__ oB,
    const unsigned long long* __restrict__ Epk,
    float emA, float emB, int j, int& CexpA, int& CexpB)
{
    const ulonglong2* wA2 = reinterpret_cast<const ulonglong2*>(wA);
    const ulonglong2* wB2 = reinterpret_cast<const ulonglong2*>(wB);
    unsigned long long a0 = 0ull, a1 = 0ull, b0 = 0ull, b1 = 0ull;
    ulonglong2 va0 = wA2[0];
    ulonglong2 vb0 = wB2[0];
    FMA2(a0, va0.x, Epk[0]); FMA2(a1, va0.y, Epk[1]);
    FMA2(b0, vb0.x, Epk[0]); FMA2(b1, vb0.y, Epk[1]);
#pragma unroll
    for (int k = 1; k < 12; k++) {
        ulonglong2 va = wA2[k];
        ulonglong2 vb = wB2[k];
        FMA2(a0, va.x, Epk[2 * k]); FMA2(a1, va.y, Epk[2 * k + 1]);
        FMA2(b0, vb.x, Epk[2 * k]); FMA2(b1, vb.y, Epk[2 * k + 1]);
    }
    unsigned long long as, bs;
    ADD2(as, a0, a1); ADD2(bs, b0, b1);
    float alo, ahi, blo, bhi;
    UNPK2(alo, ahi, as); UNPK2(blo, bhi, bs);
    unsigned int eA = ((unsigned int)va0.x) >> 23;
    unsigned int eB = ((unsigned int)vb0.x) >> 23;
    CexpA += (int)eA - 127;
    CexpB += (int)eB - 127;
    float sA = __uint_as_float((254u - eA) << 23);
    float sB = __uint_as_float((254u - eB) << 23);
    oA[j] = (alo + ahi) * (__expf(emA) * sA);
    oB[j] = (blo + bhi) * (__expf(emB) * sB);
}

// Grid layout (blockDim 48x2):
//   [0, 256)       mode 0 (time axis):  4 sids/block (2 groups x 2 seqs), 1 job
//   [256, 2304)    mode 1 (level axis): 2 jobs x 8 sids (2 groups x 4 seqs)
//   [2304, 4352)   mode 2 (rolled):     2 jobs x 8 sids
// All sids in a block share one p (mode 0) / one t (modes 1/2) -> uniform len.
__global__ __launch_bounds__(NS * GRP, 6) void crf_fwd_kernel(
    const float* __restrict__ logits,
    const float* __restrict__ trT,
    const float* __restrict__ trL,
    const float* __restrict__ trR,
    const int*   __restrict__ tags)
{
    __shared__ Smem sm;
    const int j = threadIdx.x;           // state 0..47
    const int g = threadIdx.y;           // group in block
    const int tid = g * NS + j;

    const int bid = blockIdx.x;
    int mode, mbase;
    const float* traw;
    float* outp;
    if (bid < 256)       { mode = 0; mbase = bid;                traw = trT; outp = g_llT; }
    else if (bid < 2304) { mode = 1; mbase = (bid - 256) * 2;    traw = trL; outp = g_llL; }
    else                 { mode = 2; mbase = (bid - 2304) * 2;   traw = trR; outp = g_llR; }

    // trans -> smem (coalesced), build Epk, then (modes 1/2) smem is reused.
    for (int k = tid; k < NS2; k += NS * GRP) sm.trans[k] = traw[k];
    __syncthreads();
    unsigned long long Epk[NS / 2];
#pragma unroll
    for (int k = 0; k < NS / 2; k++) {
        float lo = __expf(sm.trans[(2 * k) * NS + j]);
        float hi = __expf(sm.trans[(2 * k + 1) * NS + j]);
        PACK2(Epk[k], lo, hi);
    }
    __syncthreads();

    if (mode == 0) {
        // ---- mode 0: 2 seqs per group, sids 4*mbase + 2g + {0,1} ----
        const int sidA = 4 * mbase + 2 * g;
        const int p = sidA >> 6;
        const int len = T_DIM - p;
        const int baseA = sidA * (T_DIM * NS);
        const int baseB = baseA + T_DIM * NS;
        const int* tgA = tags + sidA * T_DIM;
        const int* tgB = tgA + T_DIM;

        float spA = 0.f, spB = 0.f;
        for (int t = j; t < len; t += NS) {
            int a0 = tgA[t];
            int b0 = tgB[t];
            spA += logits[baseA + t * NS + a0];
            spB += logits[baseB + t * NS + b0];
            if (t + 1 < len) {
                spA += sm.trans[a0 * NS + tgA[t + 1]];
                spB += sm.trans[b0 * NS + tgB[t + 1]];
            }
        }

        const float* epA = logits + baseA + j;
        const float* epB = logits + baseB + j;
        sm.u[0][g][0][j] = __expf(epA[0]);
        sm.u[0][g][1][j] = __expf(epB[0]);

        float cA[4], cB[4];
#pragma unroll
        for (int k = 0; k < 4; k++) {
            int tl = min(1 + k, len - 1);
            cA[k] = epA[tl * NS];
            cB[k] = epB[tl * NS];
        }
        int CexpA = 0, CexpB = 0, cur = 0;
        __syncthreads();

        for (int t0 = 1; t0 < len; t0 += 4) {
            float nA[4], nB[4];
#pragma unroll
            for (int k = 0; k < 4; k++) {
                int tl = min(t0 + 4 + k, len - 1);
                nA[k] = epA[tl * NS];
                nB[k] = epB[tl * NS];
            }
#pragma unroll
            for (int k = 0; k < 4; k++) {
                if (t0 + k < len) {   // block-uniform predicate
                    crf_step2(sm.u[cur][g][0], sm.u[cur][g][1],
                              sm.u[cur ^ 1][g][0], sm.u[cur ^ 1][g][1],
                              Epk, cA[k], cB[k], j, CexpA, CexpB);
                    __syncthreads();
                    cur ^= 1;
                }
            }
#pragma unroll
            for (int k = 0; k < 4; k++) { cA[k] = nA[k]; cB[k] = nB[k]; }
        }

        sm.sc[g][0][j] = spA;
        sm.sc[g][1][j] = spB;
        __syncthreads();
        if (j < 16) {
            sm.sc[g][0][j] += sm.sc[g][0][j + 16] + sm.sc[g][0][j + 32];
            sm.sc[g][1][j] += sm.sc[g][1][j + 16] + sm.sc[g][1][j + 32];
            float* uA = sm.u[cur][g][0];
            float* uB = sm.u[cur][g][1];
            uA[j] += uA[j + 16] + uA[j + 32];
            uB[j] += uB[j + 16] + uB[j + 32];
        }
        __syncthreads();
        if (j < 2) {
            const float* uf = sm.u[cur][g][j];
            const float* sf = sm.sc[g][j];
            float su = 0.f, sc = 0.f;
#pragma unroll
            for (int i = 0; i < 16; i++) { su += uf[i]; sc += sf[i]; }
            int Ce = (j == 0) ? CexpA : CexpB;
            outp[sidA + j] = (float)((double)sc - ((double)logf(su) + (double)Ce * LN2));
        }
        return;
    }

    // ---- modes 1/2: 4 seqs per group, 2 jobs of 8 sids ----
    const int SEQ_STRIDE = T_DIM * NS;
    for (int it = 0; it < 2; ++it) {
        const int m    = mbase + it;          // job: sids 8m .. 8m+7
        const int sid0 = 8 * m;
        const int t    = sid0 >> 6;           // uniform across the 8 sids
        int estride, tstride, len;
        if (mode == 1) {
            estride = B_DIM * T_DIM * NS;
            tstride = B_DIM * T_DIM;
            len     = min(P_LVL, T_DIM - t);
        } else {
            estride = B_DIM * T_DIM * NS - NS;
            tstride = B_DIM * T_DIM - 1;
            len     = min(P_LVL, t + 1);
        }
        const int b0    = (sid0 & 63) + 4 * g;             // first b of this group
        const int baseG = (b0 * T_DIM + t) * NS;           // seq s -> baseG + s*SEQ_STRIDE

        // stage all emissions (own state) for 4 seqs: 64 LDGs in flight/lane
#pragma unroll
        for (int s = 0; s < 4; s++) {
#pragma unroll
            for (int k = 0; k < P_LVL; k++) {
                int kk = min(k, len - 1);
                sm.em[g][s][k][j] = logits[baseG + s * SEQ_STRIDE + kk * estride + j];
            }
        }

        // score phase: 128 slots (8 seqs x 16 steps) over 96 threads, 2 rounds
#pragma unroll
        for (int r = 0; r < 2; r++) {
            int slot = tid + r * 96;
            if (slot < 128) {
                int sl = slot >> 4;        // local sid 0..7
                int tt = slot & 15;
                float sp = 0.f;
                if (tt < len) {
                    int bb = (sid0 & 63) + sl;
                    int tb = bb * T_DIM + t;
                    int eb = (bb * T_DIM + t) * NS;
                    int tg0 = tags[tb + tt * tstride];
                    sp = logits[eb + tt * estride + tg0];
                    if (tt + 1 < len) {
                        int tg1 = tags[tb + (tt + 1) * tstride];
                        sp += traw[tg0 * NS + tg1];   // L2-cached gather
                    }
                }
                sm.sc[sl >> 2][sl & 3][tt] = sp;
            }
        }

        // init alpha
#pragma unroll
        for (int s = 0; s < 4; s++)
            sm.u[0][g][s][j] = __expf(sm.em[g][s][0][j]);

        int Cexp[4] = {0, 0, 0, 0};
        int cur = 0;
        __syncthreads();

        for (int tt = 1; tt < len; tt++) {
            unsigned long long acc0[4], acc1[4];
            unsigned int ue[4];
#pragma unroll
            for (int s = 0; s < 4; s++) {
                const ulonglong2* w2 = reinterpret_cast<const ulonglong2*>(sm.u[cur][g][s]);
                unsigned long long a0 = 0ull, a1 = 0ull;
                ulonglong2 v0 = w2[0];
                ue[s] = ((unsigned int)v0.x) >> 23;
                FMA2(a0, v0.x, Epk[0]); FMA2(a1, v0.y, Epk[1]);
#pragma unroll
                for (int k = 1; k < 12; k++) {
                    ulonglong2 v = w2[k];
                    FMA2(a0, v.x, Epk[2 * k]); FMA2(a1, v.y, Epk[2 * k + 1]);
                }
                acc0[s] = a0; acc1[s] = a1;
            }
#pragma unroll
            for (int s = 0; s < 4; s++) {
                unsigned long long as;
                ADD2(as, acc0[s], acc1[s]);
                float lo, hi;
                UNPK2(lo, hi, as);
                Cexp[s] += (int)ue[s] - 127;
                float sscl = __uint_as_float((254u - ue[s]) << 23);
                sm.u[cur ^ 1][g][s][j] = (lo + hi) * (__expf(sm.em[g][s][tt][j]) * sscl);
            }
            __syncthreads();       // one barrier per 4 seq-steps
            cur ^= 1;
        }

        __syncthreads();   // covers len==1 (score writes -> epilogue reads)
#pragma unroll
        for (int s = 0; s < 4; s++)
            if (j < 16) {
                float* uu = sm.u[cur][g][s];
                uu[j] += uu[j + 16] + uu[j + 32];
            }
        __syncthreads();
        if (j < 4) {
            const int s = j;
            const float* uf = sm.u[cur][g][s];
            const float* sf = sm.sc[g][s];
            float su = 0.f, sc = 0.f;
#pragma unroll
            for (int i = 0; i < 16; i++) { su += uf[i]; sc += sf[i]; }
            outp[sid0 + 4 * g + s] =
                (float)((double)sc - ((double)logf(su) + (double)Cexp[s] * LN2));
        }
        __syncthreads();   // protect smem reuse by next job
    }
}

// Deterministic reduction: float4 loads, 4 independent double chains, fixed tree.
__global__ void reduce_kernel(float* __restrict__ out) {
    __shared__ double sd[256];
    const int which = blockIdx.x;
    const float* src = (which == 0) ? g_llT : (which == 1) ? g_llL : g_llR;
    const int n4 = ((which == 0) ? (P_LVL * B_DIM) : (T_DIM * B_DIM)) / 4;
    const float4* s4 = reinterpret_cast<const float4*>(src);
    double a0 = 0.0, a1 = 0.0, a2 = 0.0, a3 = 0.0;
    for (int i = threadIdx.x; i < n4; i += 256) {
        float4 v = s4[i];
        a0 += (double)v.x; a1 += (double)v.y;
        a2 += (double)v.z; a3 += (double)v.w;
    }
    sd[threadIdx.x] = (a0 + a1) + (a2 + a3);
    __syncthreads();
    for (int s = 128; s > 0; s >>= 1) {
        if (threadIdx.x < s) sd[threadIdx.x] += sd[threadIdx.x + s];
        __syncthreads();
    }
    if (threadIdx.x == 0) out[which] = (float)(-sd[0]);
}

extern "C" void kernel_launch(void* const* d_in, const int* in_sizes, int n_in,
                              void* d_out, int out_size) {
    const float* logits = (const float*)d_in[0];
    const float* trT    = (const float*)d_in[1];
    const float* trL    = (const float*)d_in[2];
    const float* trR    = (const float*)d_in[3];
    const int*   tags   = (const int*)d_in[4];
    // d_in[5] = mask: analytic (t < T - p), not read.

    dim3 blk(NS, GRP);
    crf_fwd_kernel<<<256 + 2048 + 2048, blk>>>(logits, trT, trL, trR, tags);

    reduce_kernel<<<3, 256>>>((float*)d_out);
}